// round 15
// baseline (speedup 1.0000x reference)
#include <cuda_runtime.h>
#include <cuda_fp16.h>
#include <cstdint>

#define SLEN 1024
#define BATCH 256
#define DIN 64
#define HID 128
#define KWROW 100          // words per B row: 96 real (192 fp16) + 4 pad

// h outputs for fc pass: [dir][b][t][j]
__device__ float g_h[2u * BATCH * SLEN * HID];

typedef unsigned int u32;

// pack two f32 -> f16x2 (lo16 = a0, hi16 = a1)
static __device__ __forceinline__ u32 hpack(float a0, float a1) {
    u32 r; asm("cvt.rn.f16x2.f32 %0, %1, %2;" : "=r"(r) : "f"(a1), "f"(a0)); return r;
}
static __device__ __forceinline__ float hres(float a) {
    return a - __half2float(__float2half_rn(a));
}
static __device__ __forceinline__ void mma16816h(float c[4], const u32 a[4], const u32 b[2]) {
    asm("mma.sync.aligned.m16n8k16.row.col.f32.f16.f16.f32 "
        "{%0,%1,%2,%3}, {%4,%5,%6,%7}, {%8,%9}, {%0,%1,%2,%3};"
        : "+f"(c[0]), "+f"(c[1]), "+f"(c[2]), "+f"(c[3])
        : "r"(a[0]), "r"(a[1]), "r"(a[2]), "r"(a[3]), "r"(b[0]), "r"(b[1]));
}
static __device__ __forceinline__ float tanh_mufu(float x) {
    float r; asm("tanh.approx.f32 %0, %1;" : "=f"(r) : "f"(x)); return r;
}

// ===== Recurrence: 64 blocks (2 dir x 32 batch-groups of 8), 256 threads (8 warps).
// Per step: D[j(128), b(8)] = [Whh|Wih] . [h|x], K=192.
// fp16 emulation: A = W hi/lo registers (lo only for recurrent Whh chunks),
// B = [h|x] single fp16 plane, double-buffered, word-permuted for LDS.64 frags.
// Accumulation: 7 independent chains (4 hi depth-3, 3 lo depth-3/3/2),
// inline fragment loads (no preload batch) to stay under the register ceiling.
__global__ __launch_bounds__(256, 1)
void birnn_recur(const float* __restrict__ inputs,
                 const float* __restrict__ Whh_fw, const float* __restrict__ Whh_bw,
                 const float* __restrict__ Wih_fw, const float* __restrict__ Wih_bw,
                 const float* __restrict__ bih_fw, const float* __restrict__ bhh_fw,
                 const float* __restrict__ bih_bw, const float* __restrict__ bhh_bw)
{
    __shared__ u32 C[2][8 * KWROW];     // [buf][batch 8][k-word 96 + 4 pad]

    const int tid  = threadIdx.x;
    const int lane = tid & 31;
    const int w    = tid >> 5;
    const int g  = lane >> 2;      // 0..7
    const int t4 = lane & 3;       // 0..3
    const int j0 = 16 * w;
    const int dir = blockIdx.x >> 5;
    const int bb  = (blockIdx.x & 31) * 8;

    const float* Whh = dir ? Whh_bw : Whh_fw;
    const float* Wih = dir ? Wih_bw : Wih_fw;

    // ---- static A fragments: rows j0+g, j0+g+8 over K=192 ----
    // hi for all 12 kc; lo only for the 8 recurrent (Whh) kc.
    u32 ah[12][4], al[8][4];
    #pragma unroll
    for (int kc = 0; kc < 12; ++kc) {
        const int kb = 16 * kc + 2 * t4;
        const float* r0 = (kc < 8) ? (Whh + (j0 + g) * HID + kb)
                                   : (Wih + (j0 + g) * DIN + (kb - HID));
        const float* r1 = (kc < 8) ? (Whh + (j0 + g + 8) * HID + kb)
                                   : (Wih + (j0 + g + 8) * DIN + (kb - HID));
        float2 v0 = *(const float2*)r0;
        float2 v1 = *(const float2*)r1;
        float2 v2 = *(const float2*)(r0 + 8);
        float2 v3 = *(const float2*)(r1 + 8);
        ah[kc][0] = hpack(v0.x, v0.y);
        ah[kc][1] = hpack(v1.x, v1.y);
        ah[kc][2] = hpack(v2.x, v2.y);
        ah[kc][3] = hpack(v3.x, v3.y);
        if (kc < 8) {
            al[kc][0] = hpack(hres(v0.x), hres(v0.y));
            al[kc][1] = hpack(hres(v1.x), hres(v1.y));
            al[kc][2] = hpack(hres(v2.x), hres(v2.y));
            al[kc][3] = hpack(hres(v3.x), hres(v3.y));
        }
    }

    float bias2[2];
    #pragma unroll
    for (int hh = 0; hh < 2; ++hh) {
        const int j = j0 + g + 8 * hh;
        bias2[hh] = dir ? (bih_bw[j] + bhh_bw[j]) : (bih_fw[j] + bhh_fw[j]);
    }

    // ---- zero both buffers (h0 = 0, pads 0) ----
    for (int i = tid; i < 2 * 8 * KWROW; i += 256)
        (&C[0][0])[i] = 0u;

    // ---- x loader: warp w <-> batch row w; lane covers k-dims 2*lane, 2*lane+1.
    // Word-permuted position within the kc group: q -> ((q&3)<<1)|(q>>2).
    const int t0 = dir ? (SLEN - 1) : 0;
    const int dt = dir ? -1 : 1;
    const float* xptr = inputs + ((size_t)(bb + w) * SLEN + t0) * DIN + lane * 2;
    const int xq = lane & 7;
    const int xp = ((xq & 3) << 1) | (xq >> 2);
    const int xw = w * KWROW + (8 + (lane >> 3)) * 8 + xp;

    __syncthreads();
    {
        float2 v = *(const float2*)xptr;
        C[0][xw] = hpack(v.x, v.y);
    }

    // ---- gmem h stream ----
    float* gbase = g_h + ((size_t)(dir * BATCH + bb) * SLEN + t0) * HID;
    const long gstep = (long)dt * HID;
    int goff[4];
    #pragma unroll
    for (int e = 0; e < 4; ++e)
        goff[e] = (2 * t4 + (e & 1)) * (SLEN * HID) + j0 + g + 8 * (e >> 1);

    // h smem write indices (permuted halves positions)
    int hoff[4];
    #pragma unroll
    for (int e = 0; e < 4; ++e) {
        const int b_ = 2 * t4 + (e & 1);
        const int j_ = j0 + g + 8 * (e >> 1);
        const int kc = j_ >> 4;
        const int q  = (j_ >> 1) & 7;
        const int p  = ((q & 3) << 1) | (q >> 2);
        hoff[e] = (b_ * KWROW + kc * 8 + p) * 2 + (j_ & 1);
    }

    __syncthreads();

    for (int s = 0; s < SLEN; ++s) {
        const u32* Rd = C[s & 1];

        // prefetch next x (hidden under MMA)
        float2 xn = make_float2(0.f, 0.f);
        if (s + 1 < SLEN) {
            xptr += dt * DIN;
            xn = *(const float2*)xptr;
        }

        // ---- 20 HMMA over K=192; 7 independent chains (hi x4, lo x3) ----
        float h0[4] = {0.f,0.f,0.f,0.f}, h1[4] = {0.f,0.f,0.f,0.f};
        float h2[4] = {0.f,0.f,0.f,0.f}, h3[4] = {0.f,0.f,0.f,0.f};
        float l0[4] = {0.f,0.f,0.f,0.f}, l1[4] = {0.f,0.f,0.f,0.f};
        float l2[4] = {0.f,0.f,0.f,0.f};
        #pragma unroll
        for (int kc = 0; kc < 12; ++kc) {
            uint2 bw = *(const uint2*)(Rd + g * KWROW + kc * 8 + 2 * t4);
            u32 b[2] = { bw.x, bw.y };
            float* hc = (kc < 3) ? h0 : (kc < 6) ? h1 : (kc < 9) ? h2 : h3;
            mma16816h(hc, ah[kc], b);
            if (kc < 8) {
                float* lc = (kc < 3) ? l0 : (kc < 6) ? l1 : l2;
                mma16816h(lc, al[kc], b);
            }
        }

        // ---- activate (MUFU.TANH) ----
        float v[4];
        #pragma unroll
        for (int e = 0; e < 4; ++e) {
            float sh = (h0[e] + h1[e]) + (h2[e] + h3[e]);
            float sl = (l0[e] + l1[e]) + l2[e];
            v[e] = tanh_mufu(sh + sl + bias2[e >> 1]);
        }

        // ---- write h_{s+1} fp16 into the OTHER buffer + stream fp32 to gmem ----
        unsigned short* Wu = (unsigned short*)C[(s + 1) & 1];
        #pragma unroll
        for (int e = 0; e < 4; ++e) {
            Wu[hoff[e]] = __half_as_ushort(__float2half_rn(v[e]));
            gbase[goff[e]] = v[e];
        }
        // x(t+1) into the other buffer
        C[(s + 1) & 1][xw] = hpack(xn.x, xn.y);
        gbase += gstep;

        __syncthreads();   // step-s reads done; buffer (s+1)&1 fully written
    }
}

// ===== fc head: out[b][t] = fcb + <h_fw,fcW[0:128]> + <h_bw,fcW[128:256]>
__global__ __launch_bounds__(256)
void birnn_fc(const float* __restrict__ fcW, const float* __restrict__ fcb,
              float* __restrict__ out)
{
    const int gw   = (blockIdx.x * blockDim.x + threadIdx.x) >> 5;
    const int lane = threadIdx.x & 31;
    const int b = gw >> 10;
    const int t = gw & 1023;

    const float4* hf = (const float4*)(g_h + ((size_t)b * SLEN + t) * HID);
    const float4* hb = (const float4*)(g_h + ((size_t)(BATCH + b) * SLEN + t) * HID);
    float4 a  = hf[lane];
    float4 c  = hb[lane];
    float4 wa = ((const float4*)fcW)[lane];
    float4 wb = ((const float4*)fcW)[32 + lane];

    float s = a.x*wa.x + a.y*wa.y + a.z*wa.z + a.w*wa.w
            + c.x*wb.x + c.y*wb.y + c.z*wb.z + c.w*wb.w;
    #pragma unroll
    for (int m = 16; m > 0; m >>= 1)
        s += __shfl_xor_sync(0xffffffffu, s, m);
    if (lane == 0) out[gw] = s + fcb[0];
}

extern "C" void kernel_launch(void* const* d_in, const int* in_sizes, int n_in,
                              void* d_out, int out_size)
{
    (void)in_sizes; (void)n_in; (void)out_size;
    const float* inputs = (const float*)d_in[0];
    const float* Wih_fw = (const float*)d_in[1];
    const float* Whh_fw = (const float*)d_in[2];
    const float* bih_fw = (const float*)d_in[3];
    const float* bhh_fw = (const float*)d_in[4];
    const float* Wih_bw = (const float*)d_in[5];
    const float* Whh_bw = (const float*)d_in[6];
    const float* bih_bw = (const float*)d_in[7];
    const float* bhh_bw = (const float*)d_in[8];
    const float* fcW    = (const float*)d_in[9];
    const float* fcb    = (const float*)d_in[10];
    float* out = (float*)d_out;

    birnn_recur<<<64, 256>>>(inputs, Whh_fw, Whh_bw, Wih_fw, Wih_bw,
                             bih_fw, bhh_fw, bih_bw, bhh_bw);
    birnn_fc<<<(BATCH * SLEN) / 8, 256>>>(fcW, fcb, out);
}

// round 16
// speedup vs baseline: 1.2680x; 1.2680x over previous
#include <cuda_runtime.h>
#include <cuda_fp16.h>
#include <cstdint>

#define SLEN 1024
#define BATCH 256
#define DIN 64
#define HID 128
#define KWROW 100          // words per B row: 96 real (192 fp16) + 4 pad

// h outputs for fc pass, fp16: [dir][b][t][j]
__device__ unsigned short g_h16[2u * BATCH * SLEN * HID];

typedef unsigned int u32;

// pack two f32 -> f16x2 (lo16 = a0, hi16 = a1)
static __device__ __forceinline__ u32 hpack(float a0, float a1) {
    u32 r; asm("cvt.rn.f16x2.f32 %0, %1, %2;" : "=r"(r) : "f"(a1), "f"(a0)); return r;
}
static __device__ __forceinline__ float hres(float a) {
    return a - __half2float(__float2half_rn(a));
}
static __device__ __forceinline__ void mma16816h(float c[4], const u32 a[4], const u32 b[2]) {
    asm("mma.sync.aligned.m16n8k16.row.col.f32.f16.f16.f32 "
        "{%0,%1,%2,%3}, {%4,%5,%6,%7}, {%8,%9}, {%0,%1,%2,%3};"
        : "+f"(c[0]), "+f"(c[1]), "+f"(c[2]), "+f"(c[3])
        : "r"(a[0]), "r"(a[1]), "r"(a[2]), "r"(a[3]), "r"(b[0]), "r"(b[1]));
}
static __device__ __forceinline__ float tanh_mufu(float x) {
    float r; asm("tanh.approx.f32 %0, %1;" : "=f"(r) : "f"(x)); return r;
}

// ===== Recurrence: 64 blocks (2 dir x 32 batch-groups of 8), 256 threads (8 warps).
// Per step: D[j(128), b(8)] = [Whh|Wih] . [h|x], K=192.
// fp16 emulation: A = W hi/lo registers (lo only for recurrent Whh chunks),
// B = [h|x] single fp16 plane, double-buffered, word-permuted for LDS.64 frags.
// Accumulation split into 5 named chains (max depth 4) — R13-validated layout.
__global__ __launch_bounds__(256, 1)
void birnn_recur(const float* __restrict__ inputs,
                 const float* __restrict__ Whh_fw, const float* __restrict__ Whh_bw,
                 const float* __restrict__ Wih_fw, const float* __restrict__ Wih_bw,
                 const float* __restrict__ bih_fw, const float* __restrict__ bhh_fw,
                 const float* __restrict__ bih_bw, const float* __restrict__ bhh_bw)
{
    __shared__ u32 C[2][8 * KWROW];     // [buf][batch 8][k-word 96 + 4 pad]

    const int tid  = threadIdx.x;
    const int lane = tid & 31;
    const int w    = tid >> 5;
    const int g  = lane >> 2;      // 0..7
    const int t4 = lane & 3;       // 0..3
    const int j0 = 16 * w;
    const int dir = blockIdx.x >> 5;
    const int bb  = (blockIdx.x & 31) * 8;

    const float* Whh = dir ? Whh_bw : Whh_fw;
    const float* Wih = dir ? Wih_bw : Wih_fw;

    // ---- static A fragments: rows j0+g, j0+g+8 over K=192 ----
    // hi for all 12 kc; lo only for the 8 recurrent (Whh) kc.
    u32 ah[12][4], al[8][4];
    #pragma unroll
    for (int kc = 0; kc < 12; ++kc) {
        const int kb = 16 * kc + 2 * t4;
        const float* r0 = (kc < 8) ? (Whh + (j0 + g) * HID + kb)
                                   : (Wih + (j0 + g) * DIN + (kb - HID));
        const float* r1 = (kc < 8) ? (Whh + (j0 + g + 8) * HID + kb)
                                   : (Wih + (j0 + g + 8) * DIN + (kb - HID));
        float2 v0 = *(const float2*)r0;
        float2 v1 = *(const float2*)r1;
        float2 v2 = *(const float2*)(r0 + 8);
        float2 v3 = *(const float2*)(r1 + 8);
        ah[kc][0] = hpack(v0.x, v0.y);
        ah[kc][1] = hpack(v1.x, v1.y);
        ah[kc][2] = hpack(v2.x, v2.y);
        ah[kc][3] = hpack(v3.x, v3.y);
        if (kc < 8) {
            al[kc][0] = hpack(hres(v0.x), hres(v0.y));
            al[kc][1] = hpack(hres(v1.x), hres(v1.y));
            al[kc][2] = hpack(hres(v2.x), hres(v2.y));
            al[kc][3] = hpack(hres(v3.x), hres(v3.y));
        }
    }

    float bias2[2];
    #pragma unroll
    for (int hh = 0; hh < 2; ++hh) {
        const int j = j0 + g + 8 * hh;
        bias2[hh] = dir ? (bih_bw[j] + bhh_bw[j]) : (bih_fw[j] + bhh_fw[j]);
    }

    // ---- zero both buffers (h0 = 0, pads 0) ----
    for (int i = tid; i < 2 * 8 * KWROW; i += 256)
        (&C[0][0])[i] = 0u;

    // ---- x loader: warp w <-> batch row w; lane covers k-dims 2*lane, 2*lane+1.
    // Word-permuted position within the kc group: q -> ((q&3)<<1)|(q>>2).
    const int t0 = dir ? (SLEN - 1) : 0;
    const int dt = dir ? -1 : 1;
    const float* xptr = inputs + ((size_t)(bb + w) * SLEN + t0) * DIN + lane * 2;
    const int xq = lane & 7;
    const int xp = ((xq & 3) << 1) | (xq >> 2);
    const int xw = w * KWROW + (8 + (lane >> 3)) * 8 + xp;

    __syncthreads();
    {
        float2 v = *(const float2*)xptr;
        C[0][xw] = hpack(v.x, v.y);
    }

    // ---- gmem h stream (fp16, scattered STG.16) ----
    unsigned short* gbase = g_h16 + ((size_t)(dir * BATCH + bb) * SLEN + t0) * HID;
    const long gstep = (long)dt * HID;
    int goff[4];
    #pragma unroll
    for (int e = 0; e < 4; ++e)
        goff[e] = (2 * t4 + (e & 1)) * (SLEN * HID) + j0 + g + 8 * (e >> 1);

    // h smem write indices (permuted halves positions)
    int hoff[4];
    #pragma unroll
    for (int e = 0; e < 4; ++e) {
        const int b_ = 2 * t4 + (e & 1);
        const int j_ = j0 + g + 8 * (e >> 1);
        const int kc = j_ >> 4;
        const int q  = (j_ >> 1) & 7;
        const int p  = ((q & 3) << 1) | (q >> 2);
        hoff[e] = (b_ * KWROW + kc * 8 + p) * 2 + (j_ & 1);
    }

    __syncthreads();

    for (int s = 0; s < SLEN; ++s) {
        const u32* Rd = C[s & 1];

        // prefetch next x (hidden under MMA)
        float2 xn = make_float2(0.f, 0.f);
        if (s + 1 < SLEN) {
            xptr += dt * DIN;
            xn = *(const float2*)xptr;
        }

        // ---- 20 HMMA over K=192; 5 named chains, max depth 4 ----
        float c0[4] = {0.f, 0.f, 0.f, 0.f};
        float c1[4] = {0.f, 0.f, 0.f, 0.f};
        float c2[4] = {0.f, 0.f, 0.f, 0.f};
        float c3[4] = {0.f, 0.f, 0.f, 0.f};
        float c4[4] = {0.f, 0.f, 0.f, 0.f};
        #pragma unroll
        for (int kk = 0; kk < 4; ++kk) {
            uint2 bw0 = *(const uint2*)(Rd + g * KWROW + kk * 8 + 2 * t4);           // kc = kk
            uint2 bw1 = *(const uint2*)(Rd + g * KWROW + (kk + 4) * 8 + 2 * t4);     // kc = kk+4
            uint2 bw2 = *(const uint2*)(Rd + g * KWROW + (kk + 8) * 8 + 2 * t4);     // kc = kk+8
            u32 b0[2] = { bw0.x, bw0.y };
            u32 b1[2] = { bw1.x, bw1.y };
            u32 b2[2] = { bw2.x, bw2.y };
            mma16816h(c0, ah[kk],     b0);
            mma16816h(c1, ah[kk + 4], b1);
            mma16816h(c2, ah[kk + 8], b2);
            mma16816h(c3, al[kk],     b0);
            mma16816h(c4, al[kk + 4], b1);
        }

        // ---- activate (MUFU.TANH) ----
        float v[4];
        #pragma unroll
        for (int e = 0; e < 4; ++e)
            v[e] = tanh_mufu(((c0[e] + c1[e]) + (c2[e] + c3[e])) + (c4[e] + bias2[e >> 1]));

        // ---- write h_{s+1} fp16 into the OTHER buffer + stream fp16 to gmem ----
        unsigned short* Wu = (unsigned short*)C[(s + 1) & 1];
        #pragma unroll
        for (int e = 0; e < 4; ++e) {
            const unsigned short hu = __half_as_ushort(__float2half_rn(v[e]));
            Wu[hoff[e]]    = hu;
            gbase[goff[e]] = hu;
        }
        // x(t+1) into the other buffer
        C[(s + 1) & 1][xw] = hpack(xn.x, xn.y);
        gbase += gstep;

        __syncthreads();   // step-s reads done; buffer (s+1)&1 fully written
    }
}

// ===== fc head: out[b][t] = fcb + <h_fw,fcW[0:128]> + <h_bw,fcW[128:256]>
// h stored fp16 contiguous in j; lane covers j = 4*lane .. 4*lane+3.
__global__ __launch_bounds__(256)
void birnn_fc(const float* __restrict__ fcW, const float* __restrict__ fcb,
              float* __restrict__ out)
{
    const int gw   = (blockIdx.x * blockDim.x + threadIdx.x) >> 5;
    const int lane = threadIdx.x & 31;
    const int b = gw >> 10;
    const int t = gw & 1023;

    const uint2 hf = *(const uint2*)(g_h16 + ((size_t)b * SLEN + t) * HID + lane * 4);
    const uint2 hb = *(const uint2*)(g_h16 + ((size_t)(BATCH + b) * SLEN + t) * HID + lane * 4);
    float4 wa = ((const float4*)fcW)[lane];
    float4 wb = ((const float4*)fcW)[32 + lane];

    float s;
    {
        __half2 p0 = *(const __half2*)&hf.x;
        __half2 p1 = *(const __half2*)&hf.y;
        __half2 p2 = *(const __half2*)&hb.x;
        __half2 p3 = *(const __half2*)&hb.y;
        s = __low2float(p0) * wa.x + __high2float(p0) * wa.y
          + __low2float(p1) * wa.z + __high2float(p1) * wa.w
          + __low2float(p2) * wb.x + __high2float(p2) * wb.y
          + __low2float(p3) * wb.z + __high2float(p3) * wb.w;
    }
    #pragma unroll
    for (int m = 16; m > 0; m >>= 1)
        s += __shfl_xor_sync(0xffffffffu, s, m);
    if (lane == 0) out[gw] = s + fcb[0];
}

extern "C" void kernel_launch(void* const* d_in, const int* in_sizes, int n_in,
                              void* d_out, int out_size)
{
    (void)in_sizes; (void)n_in; (void)out_size;
    const float* inputs = (const float*)d_in[0];
    const float* Wih_fw = (const float*)d_in[1];
    const float* Whh_fw = (const float*)d_in[2];
    const float* bih_fw = (const float*)d_in[3];
    const float* bhh_fw = (const float*)d_in[4];
    const float* Wih_bw = (const float*)d_in[5];
    const float* Whh_bw = (const float*)d_in[6];
    const float* bih_bw = (const float*)d_in[7];
    const float* bhh_bw = (const float*)d_in[8];
    const float* fcW    = (const float*)d_in[9];
    const float* fcb    = (const float*)d_in[10];
    float* out = (float*)d_out;

    birnn_recur<<<64, 256>>>(inputs, Whh_fw, Whh_bw, Wih_fw, Wih_bw,
                             bih_fw, bhh_fw, bih_bw, bhh_bw);
    birnn_fc<<<(BATCH * SLEN) / 8, 256>>>(fcW, fcb, out);
}

// round 17
// speedup vs baseline: 1.3519x; 1.0662x over previous
#include <cuda_runtime.h>
#include <cuda_fp16.h>
#include <cstdint>

#define SLEN 1024
#define BATCH 256
#define DIN 64
#define HID 128
#define KWROW 104          // words per B row: 96 real (192 fp16) + 8 pad (bank-conflict-free)

// h outputs for fc pass, fp16: [dir][b][t][j]
__device__ unsigned short g_h16[2u * BATCH * SLEN * HID];

typedef unsigned int u32;

// pack two f32 -> f16x2 (lo16 = a0, hi16 = a1)
static __device__ __forceinline__ u32 hpack(float a0, float a1) {
    u32 r; asm("cvt.rn.f16x2.f32 %0, %1, %2;" : "=r"(r) : "f"(a1), "f"(a0)); return r;
}
static __device__ __forceinline__ float hres(float a) {
    return a - __half2float(__float2half_rn(a));
}
static __device__ __forceinline__ void mma16816h(float c[4], const u32 a[4], const u32 b[2]) {
    asm("mma.sync.aligned.m16n8k16.row.col.f32.f16.f16.f32 "
        "{%0,%1,%2,%3}, {%4,%5,%6,%7}, {%8,%9}, {%0,%1,%2,%3};"
        : "+f"(c[0]), "+f"(c[1]), "+f"(c[2]), "+f"(c[3])
        : "r"(a[0]), "r"(a[1]), "r"(a[2]), "r"(a[3]), "r"(b[0]), "r"(b[1]));
}
static __device__ __forceinline__ float tanh_mufu(float x) {
    float r; asm("tanh.approx.f32 %0, %1;" : "=f"(r) : "f"(x)); return r;
}

// ===== Recurrence: 64 blocks (2 dir x 32 batch-groups of 8), 256 threads (8 warps).
// Per step: D[j(128), b(8)] = [Whh|Wih] . [h|x], K=192.
// fp16 emulation: A = W hi/lo registers (lo only for recurrent Whh chunks),
// B = [h|x] single fp16 plane, double-buffered, word-permuted for LDS.64 frags.
// Accumulation split into 5 named chains (max depth 4) — R13-validated layout.
__global__ __launch_bounds__(256, 1)
void birnn_recur(const float* __restrict__ inputs,
                 const float* __restrict__ Whh_fw, const float* __restrict__ Whh_bw,
                 const float* __restrict__ Wih_fw, const float* __restrict__ Wih_bw,
                 const float* __restrict__ bih_fw, const float* __restrict__ bhh_fw,
                 const float* __restrict__ bih_bw, const float* __restrict__ bhh_bw)
{
    __shared__ u32 C[2][8 * KWROW];     // [buf][batch 8][k-word 96 + 8 pad]

    const int tid  = threadIdx.x;
    const int lane = tid & 31;
    const int w    = tid >> 5;
    const int g  = lane >> 2;      // 0..7
    const int t4 = lane & 3;       // 0..3
    const int j0 = 16 * w;
    const int dir = blockIdx.x >> 5;
    const int bb  = (blockIdx.x & 31) * 8;

    const float* Whh = dir ? Whh_bw : Whh_fw;
    const float* Wih = dir ? Wih_bw : Wih_fw;

    // ---- static A fragments: rows j0+g, j0+g+8 over K=192 ----
    // hi for all 12 kc; lo only for the 8 recurrent (Whh) kc.
    u32 ah[12][4], al[8][4];
    #pragma unroll
    for (int kc = 0; kc < 12; ++kc) {
        const int kb = 16 * kc + 2 * t4;
        const float* r0 = (kc < 8) ? (Whh + (j0 + g) * HID + kb)
                                   : (Wih + (j0 + g) * DIN + (kb - HID));
        const float* r1 = (kc < 8) ? (Whh + (j0 + g + 8) * HID + kb)
                                   : (Wih + (j0 + g + 8) * DIN + (kb - HID));
        float2 v0 = *(const float2*)r0;
        float2 v1 = *(const float2*)r1;
        float2 v2 = *(const float2*)(r0 + 8);
        float2 v3 = *(const float2*)(r1 + 8);
        ah[kc][0] = hpack(v0.x, v0.y);
        ah[kc][1] = hpack(v1.x, v1.y);
        ah[kc][2] = hpack(v2.x, v2.y);
        ah[kc][3] = hpack(v3.x, v3.y);
        if (kc < 8) {
            al[kc][0] = hpack(hres(v0.x), hres(v0.y));
            al[kc][1] = hpack(hres(v1.x), hres(v1.y));
            al[kc][2] = hpack(hres(v2.x), hres(v2.y));
            al[kc][3] = hpack(hres(v3.x), hres(v3.y));
        }
    }

    float bias2[2];
    #pragma unroll
    for (int hh = 0; hh < 2; ++hh) {
        const int j = j0 + g + 8 * hh;
        bias2[hh] = dir ? (bih_bw[j] + bhh_bw[j]) : (bih_fw[j] + bhh_fw[j]);
    }

    // ---- zero both buffers (h0 = 0, pads 0) ----
    for (int i = tid; i < 2 * 8 * KWROW; i += 256)
        (&C[0][0])[i] = 0u;

    // ---- x loader: warp w <-> batch row w; lane covers k-dims 2*lane, 2*lane+1.
    // Word-permuted position within the kc group: q -> ((q&3)<<1)|(q>>2).
    const int t0 = dir ? (SLEN - 1) : 0;
    const int dt = dir ? -1 : 1;
    const float* xptr = inputs + ((size_t)(bb + w) * SLEN + t0) * DIN + lane * 2;
    const int xq = lane & 7;
    const int xp = ((xq & 3) << 1) | (xq >> 2);
    const int xw = w * KWROW + (8 + (lane >> 3)) * 8 + xp;

    __syncthreads();
    {
        float2 v = *(const float2*)xptr;
        C[0][xw] = hpack(v.x, v.y);
    }

    // ---- gmem h stream (fp16, scattered STG.16) ----
    unsigned short* gbase = g_h16 + ((size_t)(dir * BATCH + bb) * SLEN + t0) * HID;
    const long gstep = (long)dt * HID;
    int goff[4];
    #pragma unroll
    for (int e = 0; e < 4; ++e)
        goff[e] = (2 * t4 + (e & 1)) * (SLEN * HID) + j0 + g + 8 * (e >> 1);

    // h smem write indices (permuted halves positions)
    int hoff[4];
    #pragma unroll
    for (int e = 0; e < 4; ++e) {
        const int b_ = 2 * t4 + (e & 1);
        const int j_ = j0 + g + 8 * (e >> 1);
        const int kc = j_ >> 4;
        const int q  = (j_ >> 1) & 7;
        const int p  = ((q & 3) << 1) | (q >> 2);
        hoff[e] = (b_ * KWROW + kc * 8 + p) * 2 + (j_ & 1);
    }

    __syncthreads();

    for (int s = 0; s < SLEN; ++s) {
        const u32* Rd = C[s & 1];

        // prefetch next x (hidden under MMA)
        float2 xn = make_float2(0.f, 0.f);
        if (s + 1 < SLEN) {
            xptr += dt * DIN;
            xn = *(const float2*)xptr;
        }

        // ---- 20 HMMA over K=192; 5 named chains, max depth 4 ----
        float c0[4] = {0.f, 0.f, 0.f, 0.f};
        float c1[4] = {0.f, 0.f, 0.f, 0.f};
        float c2[4] = {0.f, 0.f, 0.f, 0.f};
        float c3[4] = {0.f, 0.f, 0.f, 0.f};
        float c4[4] = {0.f, 0.f, 0.f, 0.f};
        #pragma unroll
        for (int kk = 0; kk < 4; ++kk) {
            uint2 bw0 = *(const uint2*)(Rd + g * KWROW + kk * 8 + 2 * t4);           // kc = kk
            uint2 bw1 = *(const uint2*)(Rd + g * KWROW + (kk + 4) * 8 + 2 * t4);     // kc = kk+4
            uint2 bw2 = *(const uint2*)(Rd + g * KWROW + (kk + 8) * 8 + 2 * t4);     // kc = kk+8
            u32 b0[2] = { bw0.x, bw0.y };
            u32 b1[2] = { bw1.x, bw1.y };
            u32 b2[2] = { bw2.x, bw2.y };
            mma16816h(c0, ah[kk],     b0);
            mma16816h(c1, ah[kk + 4], b1);
            mma16816h(c2, ah[kk + 8], b2);
            mma16816h(c3, al[kk],     b0);
            mma16816h(c4, al[kk + 4], b1);
        }

        // ---- activate (MUFU.TANH) ----
        float v[4];
        #pragma unroll
        for (int e = 0; e < 4; ++e)
            v[e] = tanh_mufu(((c0[e] + c1[e]) + (c2[e] + c3[e])) + (c4[e] + bias2[e >> 1]));

        // ---- write h_{s+1} fp16 into the OTHER buffer + stream fp16 to gmem ----
        unsigned short* Wu = (unsigned short*)C[(s + 1) & 1];
        #pragma unroll
        for (int e = 0; e < 4; ++e) {
            const unsigned short hu = __half_as_ushort(__float2half_rn(v[e]));
            Wu[hoff[e]]    = hu;
            gbase[goff[e]] = hu;
        }
        // x(t+1) into the other buffer
        C[(s + 1) & 1][xw] = hpack(xn.x, xn.y);
        gbase += gstep;

        __syncthreads();   // step-s reads done; buffer (s+1)&1 fully written
    }
}

// ===== fc head: out[b][t] = fcb + <h_fw,fcW[0:128]> + <h_bw,fcW[128:256]>
// One warp per (b,t). Half-warp per direction; lane loads uint4 = 8 halves.
__global__ __launch_bounds__(256)
void birnn_fc(const float* __restrict__ fcW, const float* __restrict__ fcb,
              float* __restrict__ out)
{
    const int gw   = (blockIdx.x * blockDim.x + threadIdx.x) >> 5;
    const int lane = threadIdx.x & 31;
    const int b = gw >> 10;
    const int t = gw & 1023;

    const int hw   = lane >> 4;        // 0: fw, 1: bw
    const int sl   = lane & 15;        // segment lane
    const size_t base = ((size_t)(hw * BATCH + b) * SLEN + t) * HID + sl * 8;

    uint4 hq = *(const uint4*)(g_h16 + base);
    const float4 w0 = ((const float4*)fcW)[hw * 32 + sl * 2];
    const float4 w1 = ((const float4*)fcW)[hw * 32 + sl * 2 + 1];

    __half2 p0 = *(const __half2*)&hq.x;
    __half2 p1 = *(const __half2*)&hq.y;
    __half2 p2 = *(const __half2*)&hq.z;
    __half2 p3 = *(const __half2*)&hq.w;

    float s = __low2float(p0) * w0.x + __high2float(p0) * w0.y
            + __low2float(p1) * w0.z + __high2float(p1) * w0.w
            + __low2float(p2) * w1.x + __high2float(p2) * w1.y
            + __low2float(p3) * w1.z + __high2float(p3) * w1.w;

    #pragma unroll
    for (int m = 16; m > 0; m >>= 1)
        s += __shfl_xor_sync(0xffffffffu, s, m);
    if (lane == 0) out[gw] = s + fcb[0];
}

extern "C" void kernel_launch(void* const* d_in, const int* in_sizes, int n_in,
                              void* d_out, int out_size)
{
    (void)in_sizes; (void)n_in; (void)out_size;
    const float* inputs = (const float*)d_in[0];
    const float* Wih_fw = (const float*)d_in[1];
    const float* Whh_fw = (const float*)d_in[2];
    const float* bih_fw = (const float*)d_in[3];
    const float* bhh_fw = (const float*)d_in[4];
    const float* Wih_bw = (const float*)d_in[5];
    const float* Whh_bw = (const float*)d_in[6];
    const float* bih_bw = (const float*)d_in[7];
    const float* bhh_bw = (const float*)d_in[8];
    const float* fcW    = (const float*)d_in[9];
    const float* fcb    = (const float*)d_in[10];
    float* out = (float*)d_out;

    birnn_recur<<<64, 256>>>(inputs, Whh_fw, Whh_bw, Wih_fw, Wih_bw,
                             bih_fw, bhh_fw, bih_bw, bhh_bw);
    birnn_fc<<<(BATCH * SLEN) / 8, 256>>>(fcW, fcb, out);
}